// round 3
// baseline (speedup 1.0000x reference)
#include <cuda_runtime.h>
#include <cuda_bf16.h>

constexpr int N_INST = 8192;
constexpr int DIM    = 2048;
constexpr int N_CLUS = 256;
#define ALPHA_F 7.18f

// ---------------- static device scratch ----------------
__device__ int   g_counts[N_CLUS];
__device__ int   g_off[N_CLUS];
__device__ float g_validf[N_CLUS];
__device__ float g_nvalid;
__device__ int   g_rows[N_INST];
__device__ float g_residsq[N_INST];
__device__ int   g_done;

// ------- prep: hist + scan + valid + counting-sort + zero residsq (1 block, 1024 thr)
__global__ void __launch_bounds__(1024) k_prep(const int* __restrict__ clusters) {
    __shared__ int   cl[N_INST];       // 32 KB
    __shared__ int   hist_s[N_CLUS];
    __shared__ int   scan_s[N_CLUS];
    __shared__ int   cursor_s[N_CLUS];
    __shared__ float redf[N_CLUS];
    int t = threadIdx.x;
    if (t < N_CLUS) hist_s[t] = 0;
#pragma unroll
    for (int i = t; i < N_INST; i += 1024) cl[i] = clusters[i];
    // zero residsq while loads are in flight
#pragma unroll
    for (int i = t; i < N_INST; i += 1024) g_residsq[i] = 0.f;
    __syncthreads();
#pragma unroll
    for (int i = t; i < N_INST; i += 1024) atomicAdd(&hist_s[cl[i]], 1);
    __syncthreads();
    int c = 0;
    if (t < N_CLUS) { c = hist_s[t]; scan_s[t] = c; }
    __syncthreads();
    for (int off = 1; off < N_CLUS; off <<= 1) {
        int v = 0;
        if (t < N_CLUS && t >= off) v = scan_s[t - off];
        __syncthreads();
        if (t < N_CLUS) scan_s[t] += v;
        __syncthreads();
    }
    if (t < N_CLUS) {
        int excl = scan_s[t] - c;
        g_counts[t] = c;
        g_off[t] = excl;
        cursor_s[t] = excl;
        bool valid = (c >= 4);
        g_validf[t] = valid ? 1.f : 0.f;
        redf[t] = valid ? 1.f : 0.f;
    }
    __syncthreads();
    for (int s = 128; s; s >>= 1) {
        if (t < s) redf[t] += redf[t + s];
        __syncthreads();
    }
    if (t == 0) { g_nvalid = redf[0]; g_done = 0; }
    __syncthreads();
#pragma unroll
    for (int i = t; i < N_INST; i += 1024) {
        int pos = atomicAdd(&cursor_s[cl[i]], 1);
        g_rows[pos] = i;
    }
}

// ------- fused means + residual partials + last-block finalize ---------------
// grid (N_CLUS, DIM/256), block 256.
__global__ void __launch_bounds__(256) k_fused(const float* __restrict__ outputs,
                                               const int* __restrict__ clusters,
                                               float* __restrict__ out) {
    __shared__ float mean_s[256];
    __shared__ int rows_s[128];
    __shared__ float red_s[256];
    __shared__ int is_last;
    int t = threadIdx.x;
    int c = blockIdx.x;
    int col0 = blockIdx.y * 256;
    int cnt = g_counts[c];
    int base = g_off[c];

    // pass 1: mean over this cluster's rows, thread t owns col0+t (coalesced 1KB rows)
    float acc = 0.f;
    for (int j0 = 0; j0 < cnt; j0 += 128) {
        int m = cnt - j0; if (m > 128) m = 128;
        if (t < m) rows_s[t] = g_rows[base + j0 + t];
        __syncthreads();
        int j = 0;
        for (; j + 4 <= m; j += 4) {
            float a0 = outputs[(size_t)rows_s[j + 0] * DIM + col0 + t];
            float a1 = outputs[(size_t)rows_s[j + 1] * DIM + col0 + t];
            float a2 = outputs[(size_t)rows_s[j + 2] * DIM + col0 + t];
            float a3 = outputs[(size_t)rows_s[j + 3] * DIM + col0 + t];
            acc += (a0 + a1) + (a2 + a3);
        }
        for (; j < m; j++)
            acc += outputs[(size_t)rows_s[j] * DIM + col0 + t];
        __syncthreads();
    }
    mean_s[t] = acc / (float)(cnt < 1 ? 1 : cnt);
    __syncthreads();

    // pass 2: warp per row, data now L1/L2-hot; partial sum of (x-mean)^2
    int wid = t >> 5, lane = t & 31;
    const float4* m4 = (const float4*)mean_s;
    float4 mA = m4[lane];
    float4 mB = m4[lane + 32];
    for (int j = wid; j < cnt; j += 8) {
        int row = g_rows[base + j];   // broadcast load
        const float4* xp = (const float4*)(outputs + (size_t)row * DIM + col0);
        float4 xa = xp[lane];
        float4 xb = xp[lane + 32];
        float dx, s;
        dx = xa.x - mA.x; s  = dx * dx;
        dx = xa.y - mA.y; s += dx * dx;
        dx = xa.z - mA.z; s += dx * dx;
        dx = xa.w - mA.w; s += dx * dx;
        dx = xb.x - mB.x; s += dx * dx;
        dx = xb.y - mB.y; s += dx * dx;
        dx = xb.z - mB.z; s += dx * dx;
        dx = xb.w - mB.w; s += dx * dx;
#pragma unroll
        for (int o = 16; o; o >>= 1) s += __shfl_xor_sync(0xffffffffu, s, o);
        if (lane == 0) atomicAdd(&g_residsq[row], s);
    }

    // completion: ensure this block's atomics are device-visible, then count done
    __threadfence();
    __syncthreads();
    if (t == 0)
        is_last = (atomicAdd(&g_done, 1) == (int)(gridDim.x * gridDim.y) - 1);
    __syncthreads();
    if (is_last) {
        __threadfence();
        float s = 0.f;
#pragma unroll
        for (int i = t; i < N_INST; i += 256)
            s += sqrtf(g_residsq[i]) * g_validf[clusters[i]];
        red_s[t] = s;
        __syncthreads();
        for (int sh = 128; sh; sh >>= 1) {
            if (t < sh) red_s[t] += red_s[t + sh];
            __syncthreads();
        }
        if (t == 0) {
            float S = red_s[0];
            // loss = log(Nvalid-1) + alpha + 0.5/S   (stdev = S^2/num_inst)
            out[0] = logf(g_nvalid - 1.f) + ALPHA_F + 0.5f / S;
        }
    }
}

// ---------------- launch ----------------
extern "C" void kernel_launch(void* const* d_in, const int* in_sizes, int n_in,
                              void* d_out, int out_size) {
    const float* outputs  = (const float*)d_in[0];
    const int*   clusters = (const int*)d_in[1];
    float* out = (float*)d_out;

    k_prep<<<1, 1024>>>(clusters);
    k_fused<<<dim3(N_CLUS, DIM / 256), 256>>>(outputs, clusters, out);
}

// round 4
// speedup vs baseline: 1.1823x; 1.1823x over previous
#include <cuda_runtime.h>
#include <cuda_bf16.h>

constexpr int N_INST = 8192;
constexpr int DIM    = 2048;
constexpr int N_CLUS = 256;
#define ALPHA_F 7.18f

// ---------------- static device scratch ----------------
__device__ int   g_counts[N_CLUS];
__device__ int   g_off[N_CLUS];
__device__ float g_validf[N_CLUS];
__device__ float g_nvalid;
__device__ int   g_rows[N_INST];
__device__ float g_means[(size_t)N_CLUS * DIM];
__device__ float g_S;
__device__ int   g_done;

// ------- prep: hist + scan + valid + counting-sort (1 block, 1024 threads) ----
__global__ void __launch_bounds__(1024) k_prep(const int* __restrict__ clusters) {
    __shared__ int   cl[N_INST];       // 32 KB
    __shared__ int   hist_s[N_CLUS];
    __shared__ int   scan_s[N_CLUS];
    __shared__ int   cursor_s[N_CLUS];
    __shared__ float redf[N_CLUS];
    int t = threadIdx.x;
    if (t < N_CLUS) hist_s[t] = 0;
#pragma unroll
    for (int i = t; i < N_INST; i += 1024) cl[i] = clusters[i];
    __syncthreads();
#pragma unroll
    for (int i = t; i < N_INST; i += 1024) atomicAdd(&hist_s[cl[i]], 1);
    __syncthreads();
    int c = 0;
    if (t < N_CLUS) { c = hist_s[t]; scan_s[t] = c; }
    __syncthreads();
    for (int off = 1; off < N_CLUS; off <<= 1) {
        int v = 0;
        if (t < N_CLUS && t >= off) v = scan_s[t - off];
        __syncthreads();
        if (t < N_CLUS) scan_s[t] += v;
        __syncthreads();
    }
    if (t < N_CLUS) {
        int excl = scan_s[t] - c;
        g_counts[t] = c;
        g_off[t] = excl;
        cursor_s[t] = excl;
        bool valid = (c >= 4);
        g_validf[t] = valid ? 1.f : 0.f;
        redf[t] = valid ? 1.f : 0.f;
    }
    __syncthreads();
    for (int s = 128; s; s >>= 1) {
        if (t < s) redf[t] += redf[t + s];
        __syncthreads();
    }
    if (t == 0) { g_nvalid = redf[0]; g_S = 0.f; g_done = 0; }
    __syncthreads();
#pragma unroll
    for (int i = t; i < N_INST; i += 1024) {
        int pos = atomicAdd(&cursor_s[cl[i]], 1);
        g_rows[pos] = i;
    }
}

// ------- means: block (cluster c, 256-col chunk), exclusive ownership --------
__global__ void __launch_bounds__(256) k_means(const float* __restrict__ outputs) {
    __shared__ int rows_s[128];
    int t = threadIdx.x;
    int c = blockIdx.x;
    int col = blockIdx.y * 256 + t;
    int cnt = g_counts[c];
    int base = g_off[c];
    float acc = 0.f;
    for (int j0 = 0; j0 < cnt; j0 += 128) {
        int m = cnt - j0; if (m > 128) m = 128;
        if (t < m) rows_s[t] = g_rows[base + j0 + t];
        __syncthreads();
        int j = 0;
        for (; j + 8 <= m; j += 8) {
            float a0 = outputs[(size_t)rows_s[j + 0] * DIM + col];
            float a1 = outputs[(size_t)rows_s[j + 1] * DIM + col];
            float a2 = outputs[(size_t)rows_s[j + 2] * DIM + col];
            float a3 = outputs[(size_t)rows_s[j + 3] * DIM + col];
            float a4 = outputs[(size_t)rows_s[j + 4] * DIM + col];
            float a5 = outputs[(size_t)rows_s[j + 5] * DIM + col];
            float a6 = outputs[(size_t)rows_s[j + 6] * DIM + col];
            float a7 = outputs[(size_t)rows_s[j + 7] * DIM + col];
            acc += ((a0 + a1) + (a2 + a3)) + ((a4 + a5) + (a6 + a7));
        }
        for (; j < m; j++)
            acc += outputs[(size_t)rows_s[j] * DIM + col];
        __syncthreads();
    }
    g_means[(size_t)c * DIM + col] = acc / (float)(cnt < 1 ? 1 : cnt);
}

// ------- resid: streaming warp-per-row, L2-hot; last-block finalize ----------
__global__ void __launch_bounds__(256) k_resid(const float* __restrict__ outputs,
                                               const int* __restrict__ clusters,
                                               float* __restrict__ out) {
    __shared__ float ws[8];
    __shared__ float red_s[256];
    __shared__ int is_last;
    int t = threadIdx.x;
    int wid = t >> 5, lane = t & 31;
    int row = blockIdx.x * 8 + wid;
    int ci = clusters[row];
    const float4* xp = (const float4*)(outputs + (size_t)row * DIM);
    const float4* mp = (const float4*)(g_means + (size_t)ci * DIM);
    float s = 0.f;
#pragma unroll
    for (int i = 0; i < 16; i++) {
        float4 x = xp[i * 32 + lane];
        float4 m = mp[i * 32 + lane];
        float dx = x.x - m.x, dy = x.y - m.y, dz = x.z - m.z, dw = x.w - m.w;
        s += dx * dx + dy * dy + dz * dz + dw * dw;
    }
#pragma unroll
    for (int o = 16; o; o >>= 1) s += __shfl_xor_sync(0xffffffffu, s, o);
    if (lane == 0) ws[wid] = sqrtf(s) * g_validf[ci];
    __syncthreads();
    if (t == 0) {
        float b = 0.f;
#pragma unroll
        for (int i = 0; i < 8; i++) b += ws[i];
        atomicAdd(&g_S, b);
        __threadfence();
        is_last = (atomicAdd(&g_done, 1) == (int)gridDim.x - 1);
    }
    __syncthreads();
    if (is_last && t == 0) {
        __threadfence();
        // loss = log(Nvalid-1) + alpha + 0.5/S    (stdev = S^2/num_inst quirk)
        out[0] = logf(g_nvalid - 1.f) + ALPHA_F + 0.5f / g_S;
    }
    (void)red_s;
}

// ---------------- launch ----------------
extern "C" void kernel_launch(void* const* d_in, const int* in_sizes, int n_in,
                              void* d_out, int out_size) {
    const float* outputs  = (const float*)d_in[0];
    const int*   clusters = (const int*)d_in[1];
    float* out = (float*)d_out;

    k_prep<<<1, 1024>>>(clusters);
    k_means<<<dim3(N_CLUS, DIM / 256), 256>>>(outputs);
    k_resid<<<N_INST / 8, 256>>>(outputs, clusters, out);
}

// round 5
// speedup vs baseline: 1.5664x; 1.3249x over previous
#include <cuda_runtime.h>
#include <cuda_bf16.h>

constexpr int N_INST = 8192;
constexpr int DIM    = 2048;
constexpr int N_CLUS = 256;
constexpr int WIN    = 2048;     // label scan window (smem list can never overflow)
#define ALPHA_F 7.18f

// ---------------- static device scratch ----------------
__device__ float g_validf[N_CLUS];
__device__ float g_means[(size_t)N_CLUS * DIM];
__device__ float g_S;
__device__ int   g_done;

// ------- means: block (cluster c, 1024-col chunk); self-built row list -------
__global__ void __launch_bounds__(256) k_means(const float* __restrict__ outputs,
                                               const int* __restrict__ clusters) {
    __shared__ int rows_s[WIN];
    __shared__ int nmatch_s;
    int t = threadIdx.x;
    int c = blockIdx.x;
    size_t col = (size_t)blockIdx.y * 1024 + t * 4;
    float4 acc = make_float4(0.f, 0.f, 0.f, 0.f);
    int total = 0;

    for (int w = 0; w < N_INST; w += WIN) {
        if (t == 0) nmatch_s = 0;
        __syncthreads();
#pragma unroll
        for (int i = t; i < WIN; i += 256) {
            if (clusters[w + i] == c) {
                int p = atomicAdd(&nmatch_s, 1);
                rows_s[p] = w + i;
            }
        }
        __syncthreads();
        int m = nmatch_s;
        total += m;
        int j = 0;
        for (; j + 4 <= m; j += 4) {
            float4 a0 = *(const float4*)&outputs[(size_t)rows_s[j + 0] * DIM + col];
            float4 a1 = *(const float4*)&outputs[(size_t)rows_s[j + 1] * DIM + col];
            float4 a2 = *(const float4*)&outputs[(size_t)rows_s[j + 2] * DIM + col];
            float4 a3 = *(const float4*)&outputs[(size_t)rows_s[j + 3] * DIM + col];
            acc.x += (a0.x + a1.x) + (a2.x + a3.x);
            acc.y += (a0.y + a1.y) + (a2.y + a3.y);
            acc.z += (a0.z + a1.z) + (a2.z + a3.z);
            acc.w += (a0.w + a1.w) + (a2.w + a3.w);
        }
        for (; j < m; j++) {
            float4 a = *(const float4*)&outputs[(size_t)rows_s[j] * DIM + col];
            acc.x += a.x; acc.y += a.y; acc.z += a.z; acc.w += a.w;
        }
        __syncthreads();
    }

    float inv = 1.f / (float)(total < 1 ? 1 : total);
    *(float4*)&g_means[(size_t)c * DIM + col] =
        make_float4(acc.x * inv, acc.y * inv, acc.z * inv, acc.w * inv);

    if (blockIdx.y == 0 && t == 0) {
        g_validf[c] = (total >= 4) ? 1.f : 0.f;
        if (c == 0) { g_S = 0.f; g_done = 0; }
    }
}

// ------- resid: streaming warp-per-row, L2-hot; last-block finalize ----------
__global__ void __launch_bounds__(256) k_resid(const float* __restrict__ outputs,
                                               const int* __restrict__ clusters,
                                               float* __restrict__ out) {
    __shared__ float ws[8];
    __shared__ float red_s[256];
    __shared__ int is_last;
    int t = threadIdx.x;
    int wid = t >> 5, lane = t & 31;
    int row = blockIdx.x * 8 + wid;
    int ci = clusters[row];
    const float4* xp = (const float4*)(outputs + (size_t)row * DIM);
    const float4* mp = (const float4*)(g_means + (size_t)ci * DIM);
    float s = 0.f;
#pragma unroll
    for (int i = 0; i < 16; i++) {
        float4 x = xp[i * 32 + lane];
        float4 m = mp[i * 32 + lane];
        float dx = x.x - m.x, dy = x.y - m.y, dz = x.z - m.z, dw = x.w - m.w;
        s += dx * dx + dy * dy + dz * dz + dw * dw;
    }
#pragma unroll
    for (int o = 16; o; o >>= 1) s += __shfl_xor_sync(0xffffffffu, s, o);
    if (lane == 0) ws[wid] = sqrtf(s) * g_validf[ci];
    __syncthreads();
    if (t == 0) {
        float b = 0.f;
#pragma unroll
        for (int i = 0; i < 8; i++) b += ws[i];
        atomicAdd(&g_S, b);
        __threadfence();
        is_last = (atomicAdd(&g_done, 1) == (int)gridDim.x - 1);
    }
    __syncthreads();
    if (is_last) {
        __threadfence();
        red_s[t] = g_validf[t];          // block has exactly 256 threads
        __syncthreads();
        for (int sh = 128; sh; sh >>= 1) {
            if (t < sh) red_s[t] += red_s[t + sh];
            __syncthreads();
        }
        if (t == 0) {
            float nvalid = red_s[0];
            // loss = log(Nvalid-1) + alpha + 0.5/S   (stdev = S^2/num_inst quirk)
            out[0] = logf(nvalid - 1.f) + ALPHA_F + 0.5f / g_S;
        }
    }
}

// ---------------- launch ----------------
extern "C" void kernel_launch(void* const* d_in, const int* in_sizes, int n_in,
                              void* d_out, int out_size) {
    const float* outputs  = (const float*)d_in[0];
    const int*   clusters = (const int*)d_in[1];
    float* out = (float*)d_out;

    k_means<<<dim3(N_CLUS, 2), 256>>>(outputs, clusters);
    k_resid<<<N_INST / 8, 256>>>(outputs, clusters, out);
}

// round 6
// speedup vs baseline: 1.5824x; 1.0102x over previous
#include <cuda_runtime.h>
#include <cuda_bf16.h>

constexpr int N_INST = 8192;
constexpr int DIM    = 2048;
constexpr int N_CLUS = 256;
constexpr int WIN    = 2048;     // label scan window (smem list can never overflow)
#define ALPHA_F 7.18f

// ---------------- static device scratch ----------------
__device__ float g_validf[N_CLUS];
__device__ float g_means[(size_t)N_CLUS * DIM];
__device__ float g_S;
__device__ int   g_done;

// ------- means: block (cluster c, 1024-col chunk); self-built row list -------
__global__ void __launch_bounds__(256) k_means(const float* __restrict__ outputs,
                                               const int* __restrict__ clusters) {
    __shared__ int rows_s[WIN];
    __shared__ int nmatch_s;
    int t = threadIdx.x;
    int c = blockIdx.x;
    size_t col = (size_t)blockIdx.y * 1024 + t * 4;
    float4 acc = make_float4(0.f, 0.f, 0.f, 0.f);
    int total = 0;

    for (int w = 0; w < N_INST; w += WIN) {
        if (t == 0) nmatch_s = 0;
        __syncthreads();
#pragma unroll
        for (int i = t; i < WIN; i += 256) {
            if (clusters[w + i] == c) {
                int p = atomicAdd(&nmatch_s, 1);
                rows_s[p] = w + i;
            }
        }
        __syncthreads();
        int m = nmatch_s;
        total += m;
        int j = 0;
        for (; j + 8 <= m; j += 8) {
            float4 a0 = *(const float4*)&outputs[(size_t)rows_s[j + 0] * DIM + col];
            float4 a1 = *(const float4*)&outputs[(size_t)rows_s[j + 1] * DIM + col];
            float4 a2 = *(const float4*)&outputs[(size_t)rows_s[j + 2] * DIM + col];
            float4 a3 = *(const float4*)&outputs[(size_t)rows_s[j + 3] * DIM + col];
            float4 a4 = *(const float4*)&outputs[(size_t)rows_s[j + 4] * DIM + col];
            float4 a5 = *(const float4*)&outputs[(size_t)rows_s[j + 5] * DIM + col];
            float4 a6 = *(const float4*)&outputs[(size_t)rows_s[j + 6] * DIM + col];
            float4 a7 = *(const float4*)&outputs[(size_t)rows_s[j + 7] * DIM + col];
            acc.x += ((a0.x + a1.x) + (a2.x + a3.x)) + ((a4.x + a5.x) + (a6.x + a7.x));
            acc.y += ((a0.y + a1.y) + (a2.y + a3.y)) + ((a4.y + a5.y) + (a6.y + a7.y));
            acc.z += ((a0.z + a1.z) + (a2.z + a3.z)) + ((a4.z + a5.z) + (a6.z + a7.z));
            acc.w += ((a0.w + a1.w) + (a2.w + a3.w)) + ((a4.w + a5.w) + (a6.w + a7.w));
        }
        for (; j < m; j++) {
            float4 a = *(const float4*)&outputs[(size_t)rows_s[j] * DIM + col];
            acc.x += a.x; acc.y += a.y; acc.z += a.z; acc.w += a.w;
        }
        __syncthreads();
    }

    float inv = 1.f / (float)(total < 1 ? 1 : total);
    *(float4*)&g_means[(size_t)c * DIM + col] =
        make_float4(acc.x * inv, acc.y * inv, acc.z * inv, acc.w * inv);

    if (blockIdx.y == 0 && t == 0) {
        g_validf[c] = (total >= 4) ? 1.f : 0.f;
        if (c == 0) { g_S = 0.f; g_done = 0; }
    }
}

// ------- resid: warp-per-row, 8-deep front-batched loads; last-block finalize
__global__ void __launch_bounds__(256) k_resid(const float* __restrict__ outputs,
                                               const int* __restrict__ clusters,
                                               float* __restrict__ out) {
    __shared__ float ws[8];
    __shared__ float red_s[256];
    __shared__ int is_last;
    int t = threadIdx.x;
    int wid = t >> 5, lane = t & 31;
    int row = blockIdx.x * 8 + wid;
    int ci = clusters[row];
    const float4* xp = (const float4*)(outputs + (size_t)row * DIM) + lane;
    const float4* mp = (const float4*)(g_means + (size_t)ci * DIM) + lane;
    float s = 0.f;
    for (int ch = 0; ch < 4; ch++) {
        int b = ch * 128;
        float4 x0 = xp[b];
        float4 x1 = xp[b + 32];
        float4 x2 = xp[b + 64];
        float4 x3 = xp[b + 96];
        float4 m0 = mp[b];
        float4 m1 = mp[b + 32];
        float4 m2 = mp[b + 64];
        float4 m3 = mp[b + 96];
        float d;
        d = x0.x - m0.x; s += d * d;  d = x0.y - m0.y; s += d * d;
        d = x0.z - m0.z; s += d * d;  d = x0.w - m0.w; s += d * d;
        d = x1.x - m1.x; s += d * d;  d = x1.y - m1.y; s += d * d;
        d = x1.z - m1.z; s += d * d;  d = x1.w - m1.w; s += d * d;
        d = x2.x - m2.x; s += d * d;  d = x2.y - m2.y; s += d * d;
        d = x2.z - m2.z; s += d * d;  d = x2.w - m2.w; s += d * d;
        d = x3.x - m3.x; s += d * d;  d = x3.y - m3.y; s += d * d;
        d = x3.z - m3.z; s += d * d;  d = x3.w - m3.w; s += d * d;
    }
#pragma unroll
    for (int o = 16; o; o >>= 1) s += __shfl_xor_sync(0xffffffffu, s, o);
    if (lane == 0) ws[wid] = sqrtf(s) * g_validf[ci];
    __syncthreads();
    if (t == 0) {
        float b = 0.f;
#pragma unroll
        for (int i = 0; i < 8; i++) b += ws[i];
        atomicAdd(&g_S, b);
        __threadfence();
        is_last = (atomicAdd(&g_done, 1) == (int)gridDim.x - 1);
    }
    __syncthreads();
    if (is_last) {
        __threadfence();
        red_s[t] = g_validf[t];          // block has exactly 256 threads
        __syncthreads();
        for (int sh = 128; sh; sh >>= 1) {
            if (t < sh) red_s[t] += red_s[t + sh];
            __syncthreads();
        }
        if (t == 0) {
            float nvalid = red_s[0];
            // loss = log(Nvalid-1) + alpha + 0.5/S   (stdev = S^2/num_inst quirk)
            out[0] = logf(nvalid - 1.f) + ALPHA_F + 0.5f / g_S;
        }
    }
}

// ---------------- launch ----------------
extern "C" void kernel_launch(void* const* d_in, const int* in_sizes, int n_in,
                              void* d_out, int out_size) {
    const float* outputs  = (const float*)d_in[0];
    const int*   clusters = (const int*)d_in[1];
    float* out = (float*)d_out;

    k_means<<<dim3(N_CLUS, 2), 256>>>(outputs, clusters);
    k_resid<<<N_INST / 8, 256>>>(outputs, clusters, out);
}

// round 7
// speedup vs baseline: 1.7043x; 1.0770x over previous
#include <cuda_runtime.h>
#include <cuda_bf16.h>

constexpr int N_INST = 8192;
constexpr int DIM    = 2048;
constexpr int N_CLUS = 256;
constexpr int WIN    = 2048;     // label scan window (smem list can never overflow)
#define ALPHA_F 7.18f

// ---------------- static device scratch ----------------
__device__ float g_validf[N_CLUS];
__device__ float g_means[(size_t)N_CLUS * DIM];
__device__ float g_S;
__device__ int   g_done;

// ------- means: block (cluster c, 1024-col chunk); self-built row list -------
__global__ void __launch_bounds__(256) k_means(const float* __restrict__ outputs,
                                               const int* __restrict__ clusters) {
    __shared__ int rows_s[WIN];
    __shared__ int nmatch_s;
    int t = threadIdx.x;
    int c = blockIdx.x;
    size_t col = (size_t)blockIdx.y * 1024 + t * 4;
    float4 acc = make_float4(0.f, 0.f, 0.f, 0.f);
    int total = 0;

    for (int w = 0; w < N_INST; w += WIN) {
        if (t == 0) nmatch_s = 0;
        __syncthreads();
#pragma unroll
        for (int i = t; i < WIN; i += 256) {
            if (clusters[w + i] == c) {
                int p = atomicAdd(&nmatch_s, 1);
                rows_s[p] = w + i;
            }
        }
        __syncthreads();
        int m = nmatch_s;
        total += m;
        int j = 0;
        for (; j + 8 <= m; j += 8) {
            float4 a0 = *(const float4*)&outputs[(size_t)rows_s[j + 0] * DIM + col];
            float4 a1 = *(const float4*)&outputs[(size_t)rows_s[j + 1] * DIM + col];
            float4 a2 = *(const float4*)&outputs[(size_t)rows_s[j + 2] * DIM + col];
            float4 a3 = *(const float4*)&outputs[(size_t)rows_s[j + 3] * DIM + col];
            float4 a4 = *(const float4*)&outputs[(size_t)rows_s[j + 4] * DIM + col];
            float4 a5 = *(const float4*)&outputs[(size_t)rows_s[j + 5] * DIM + col];
            float4 a6 = *(const float4*)&outputs[(size_t)rows_s[j + 6] * DIM + col];
            float4 a7 = *(const float4*)&outputs[(size_t)rows_s[j + 7] * DIM + col];
            acc.x += ((a0.x + a1.x) + (a2.x + a3.x)) + ((a4.x + a5.x) + (a6.x + a7.x));
            acc.y += ((a0.y + a1.y) + (a2.y + a3.y)) + ((a4.y + a5.y) + (a6.y + a7.y));
            acc.z += ((a0.z + a1.z) + (a2.z + a3.z)) + ((a4.z + a5.z) + (a6.z + a7.z));
            acc.w += ((a0.w + a1.w) + (a2.w + a3.w)) + ((a4.w + a5.w) + (a6.w + a7.w));
        }
        for (; j < m; j++) {
            float4 a = *(const float4*)&outputs[(size_t)rows_s[j] * DIM + col];
            acc.x += a.x; acc.y += a.y; acc.z += a.z; acc.w += a.w;
        }
        __syncthreads();
    }

    float inv = 1.f / (float)(total < 1 ? 1 : total);
    *(float4*)&g_means[(size_t)c * DIM + col] =
        make_float4(acc.x * inv, acc.y * inv, acc.z * inv, acc.w * inv);

    if (blockIdx.y == 0 && t == 0) {
        g_validf[c] = (total >= 4) ? 1.f : 0.f;
        if (c == 0) { g_S = 0.f; g_done = 0; }
    }
}

// ------- resid: 2 rows per warp (4 independent load streams); finalize -------
__global__ void __launch_bounds__(256) k_resid(const float* __restrict__ outputs,
                                               const int* __restrict__ clusters,
                                               float* __restrict__ out) {
    __shared__ float ws[16];
    __shared__ float red_s[256];
    __shared__ int is_last;
    int t = threadIdx.x;
    int wid = t >> 5, lane = t & 31;
    int rowA = blockIdx.x * 16 + wid * 2;
    int rowB = rowA + 1;
    int cA = clusters[rowA];
    int cB = clusters[rowB];
    const float4* xA = (const float4*)(outputs + (size_t)rowA * DIM) + lane;
    const float4* xB = (const float4*)(outputs + (size_t)rowB * DIM) + lane;
    const float4* mA = (const float4*)(g_means + (size_t)cA * DIM) + lane;
    const float4* mB = (const float4*)(g_means + (size_t)cB * DIM) + lane;
    float sA = 0.f, sB = 0.f;
#pragma unroll
    for (int i = 0; i < 16; i += 2) {
        float4 xa0 = xA[i * 32];
        float4 xb0 = xB[i * 32];
        float4 xa1 = xA[(i + 1) * 32];
        float4 xb1 = xB[(i + 1) * 32];
        float4 ma0 = mA[i * 32];
        float4 mb0 = mB[i * 32];
        float4 ma1 = mA[(i + 1) * 32];
        float4 mb1 = mB[(i + 1) * 32];
        float d;
        d = xa0.x - ma0.x; sA += d * d;  d = xa0.y - ma0.y; sA += d * d;
        d = xa0.z - ma0.z; sA += d * d;  d = xa0.w - ma0.w; sA += d * d;
        d = xb0.x - mb0.x; sB += d * d;  d = xb0.y - mb0.y; sB += d * d;
        d = xb0.z - mb0.z; sB += d * d;  d = xb0.w - mb0.w; sB += d * d;
        d = xa1.x - ma1.x; sA += d * d;  d = xa1.y - ma1.y; sA += d * d;
        d = xa1.z - ma1.z; sA += d * d;  d = xa1.w - ma1.w; sA += d * d;
        d = xb1.x - mb1.x; sB += d * d;  d = xb1.y - mb1.y; sB += d * d;
        d = xb1.z - mb1.z; sB += d * d;  d = xb1.w - mb1.w; sB += d * d;
    }
#pragma unroll
    for (int o = 16; o; o >>= 1) {
        sA += __shfl_xor_sync(0xffffffffu, sA, o);
        sB += __shfl_xor_sync(0xffffffffu, sB, o);
    }
    if (lane == 0) {
        ws[wid * 2]     = sqrtf(sA) * g_validf[cA];
        ws[wid * 2 + 1] = sqrtf(sB) * g_validf[cB];
    }
    __syncthreads();
    if (t == 0) {
        float b = 0.f;
#pragma unroll
        for (int i = 0; i < 16; i++) b += ws[i];
        atomicAdd(&g_S, b);
        __threadfence();
        is_last = (atomicAdd(&g_done, 1) == (int)gridDim.x - 1);
    }
    __syncthreads();
    if (is_last) {
        __threadfence();
        red_s[t] = g_validf[t];          // block has exactly 256 threads
        __syncthreads();
        for (int sh = 128; sh; sh >>= 1) {
            if (t < sh) red_s[t] += red_s[t + sh];
            __syncthreads();
        }
        if (t == 0) {
            float nvalid = red_s[0];
            // loss = log(Nvalid-1) + alpha + 0.5/S   (stdev = S^2/num_inst quirk)
            out[0] = logf(nvalid - 1.f) + ALPHA_F + 0.5f / g_S;
        }
    }
}

// ---------------- launch ----------------
extern "C" void kernel_launch(void* const* d_in, const int* in_sizes, int n_in,
                              void* d_out, int out_size) {
    const float* outputs  = (const float*)d_in[0];
    const int*   clusters = (const int*)d_in[1];
    float* out = (float*)d_out;

    k_means<<<dim3(N_CLUS, 2), 256>>>(outputs, clusters);
    k_resid<<<N_INST / 16, 256>>>(outputs, clusters, out);
}